// round 16
// baseline (speedup 1.0000x reference)
#include <cuda_runtime.h>
#include <math.h>
#include <float.h>
#include <stdint.h>

#define B      32
#define HW     4096
#define D      256
#define NPQ    512
#define NQ     3
#define NPOS   10
#define NPAIR  30              // NQ * NPOS per batch
#define CHUNK  256             // rows per attn block
#define NCHUNK (HW / CHUNK)    // 16
#define NCAND  (NCHUNK * NPOS) // 160 candidates per (b,q)

#define STAGE_ROWS  16
#define NSTAGE      2
#define NITER       (CHUNK / STAGE_ROWS)          // 16
#define STAGE_BYTES (STAGE_ROWS * D * 4)          // 16384

// ---- scratch (device globals; no allocation allowed) ----
__device__ float g_cand_val[B * NQ * NCAND];
__device__ int   g_cand_idx[B * NQ * NCAND];
__device__ float g_part[B * NPAIR];

// ---------------------------------------------------------------------------
// mbarrier / bulk-copy primitives
// ---------------------------------------------------------------------------
__device__ __forceinline__ uint32_t smem_u32(const void* p) {
    return (uint32_t)__cvta_generic_to_shared(p);
}

__device__ __forceinline__ void mbar_init(uint32_t bar, uint32_t count) {
    asm volatile("mbarrier.init.shared.b64 [%0], %1;" :: "r"(bar), "r"(count) : "memory");
}

__device__ __forceinline__ void mbar_expect_tx(uint32_t bar, uint32_t bytes) {
    asm volatile("mbarrier.arrive.expect_tx.shared.b64 _, [%0], %1;"
                 :: "r"(bar), "r"(bytes) : "memory");
}

__device__ __forceinline__ void mbar_arrive(uint32_t bar) {
    asm volatile("mbarrier.arrive.shared.b64 _, [%0];" :: "r"(bar) : "memory");
}

__device__ __forceinline__ void mbar_wait(uint32_t bar, uint32_t parity) {
    asm volatile(
        "{\n\t"
        ".reg .pred P;\n\t"
        "LWAIT%=:\n\t"
        "mbarrier.try_wait.parity.acquire.cta.shared::cta.b64 P, [%0], %1;\n\t"
        "@!P bra LWAIT%=;\n\t"
        "}"
        :: "r"(bar), "r"(parity) : "memory");
}

__device__ __forceinline__ void bulk_copy_g2s(uint32_t dst_smem, const void* src_gmem,
                                              uint32_t bytes, uint32_t bar) {
    asm volatile(
        "cp.async.bulk.shared::cta.global.mbarrier::complete_tx::bytes [%0], [%1], %2, [%3];"
        :: "r"(dst_smem), "l"(src_gmem), "r"(bytes), "r"(bar) : "memory");
}

// ---------------------------------------------------------------------------
// rand_idx dtype detection, block-local: int64 nonneg (<2^31) -> odd 32-bit
// words of the first 48 entries are all 0. Reads stay within 384 B (valid for
// both int32[96] and int64[96] layouts). Must be called by ALL threads.
// ---------------------------------------------------------------------------
__device__ __forceinline__ int detect_is64(const int* __restrict__ r32, int tid) {
    int v = (tid < 48) ? r32[2 * tid + 1] : 0;
    int any = __syncthreads_or(v != 0);
    return any == 0;
}

__device__ __forceinline__ int load_idx(const int* __restrict__ r32, int i, int is64) {
    return is64 ? r32[2 * i] : r32[i];     // little-endian low word
}

// ---------------------------------------------------------------------------
// Kernel A: attn scores for a 256-row chunk + per-chunk top-10 candidates.
// grid (B, 16) = 512, 256 threads (8 warps), 4 CTAs/SM -> single wave.
// TMA bulk-copy 2-stage pipeline: tid 0 streams 16-row (16 KB) stages of
// z_pos into smem (mbarrier expect_tx / full-empty ring); the 8 warps
// compute 2 rows each per stage from smem (LDS.128, conflict-free), with a
// packed 2-row x 3-query butterfly reduction (18 shuffles).
// Phase B: warps 0..2 extract the chunk-local top-10 per query.
// ---------------------------------------------------------------------------
__global__ void __launch_bounds__(256, 4) attn_kernel(
    const float* __restrict__ z,
    const float* __restrict__ z_pos,
    const int*  __restrict__ ridx)
{
    const int b     = blockIdx.x;
    const int chunk = blockIdx.y;
    const int tid   = threadIdx.x;
    const int w     = tid >> 5;
    const int lane  = tid & 31;

    __shared__ __align__(128) float stage[NSTAGE][STAGE_ROWS * D];   // 32 KB
    __shared__ float scores[NQ][CHUNK];                              // 3 KB
    __shared__ int   qrow[NQ];
    __shared__ __align__(8) unsigned long long mbar[2 * NSTAGE];     // full[s], empty[s]

    const int is64 = detect_is64(ridx, tid);
    if (tid < NQ) qrow[tid] = load_idx(ridx, b * NQ + tid, is64);

    const uint32_t mb_full  = smem_u32(&mbar[0]);
    const uint32_t mb_empty = smem_u32(&mbar[NSTAGE]);
    if (tid == 0) {
#pragma unroll
        for (int s = 0; s < NSTAGE; s++) {
            mbar_init(mb_full  + 8 * s, 1);     // producer arrive+expect_tx
            mbar_init(mb_empty + 8 * s, 256);   // all threads arrive
        }
    }
    __syncthreads();

    // Per-lane query registers: cols [lane*8, lane*8+8)
    const float* zb = z + (size_t)b * HW * D;
    float q[NQ][8];
#pragma unroll
    for (int s = 0; s < NQ; s++) {
        const float4* qp = (const float4*)(zb + (size_t)qrow[s] * D + lane * 8);
        float4 a = qp[0], c = qp[1];
        q[s][0] = a.x; q[s][1] = a.y; q[s][2] = a.z; q[s][3] = a.w;
        q[s][4] = c.x; q[s][5] = c.y; q[s][6] = c.z; q[s][7] = c.w;
    }

    const float* src = z_pos + (size_t)b * HW * D + (size_t)chunk * CHUNK * D;
    const int    rbase = chunk * CHUNK;

    // prologue: fill both stages
    if (tid == 0) {
#pragma unroll
        for (int s = 0; s < NSTAGE; s++) {
            mbar_expect_tx(mb_full + 8 * s, STAGE_BYTES);
            bulk_copy_g2s(smem_u32(stage[s]), src + (size_t)s * STAGE_ROWS * D,
                          STAGE_BYTES, mb_full + 8 * s);
        }
    }

    for (int i = 0; i < NITER; i++) {
        const int      slot = i & (NSTAGE - 1);
        const uint32_t ph   = (uint32_t)((i / NSTAGE) & 1);

        mbar_wait(mb_full + 8 * slot, ph);

        // two rows per warp: local rows 2w, 2w+1 of this stage
        const float* st = stage[slot];
        const float4* r0p = (const float4*)(st + (2 * w)     * D + lane * 8);
        const float4* r1p = (const float4*)(st + (2 * w + 1) * D + lane * 8);
        float4 x0 = r0p[0], x1 = r0p[1];
        float4 y0 = r1p[0], y1 = r1p[1];

        float s0[NQ], s1[NQ];
#pragma unroll
        for (int sq = 0; sq < NQ; sq++) {
            s0[sq] = x0.x * q[sq][0] + x0.y * q[sq][1] + x0.z * q[sq][2] + x0.w * q[sq][3]
                   + x1.x * q[sq][4] + x1.y * q[sq][5] + x1.z * q[sq][6] + x1.w * q[sq][7];
            s1[sq] = y0.x * q[sq][0] + y0.y * q[sq][1] + y0.z * q[sq][2] + y0.w * q[sq][3]
                   + y1.x * q[sq][4] + y1.y * q[sq][5] + y1.z * q[sq][6] + y1.w * q[sq][7];
        }

        // packed 2-row reduce: lanes 0-15 carry row 2w, lanes 16-31 carry row 2w+1
        float ev[NQ];
#pragma unroll
        for (int sq = 0; sq < NQ; sq++) {
            float t0 = s0[sq] + __shfl_xor_sync(0xFFFFFFFFu, s0[sq], 16);
            float t1 = s1[sq] + __shfl_xor_sync(0xFFFFFFFFu, s1[sq], 16);
            float c  = (lane & 16) ? t1 : t0;
            c += __shfl_xor_sync(0xFFFFFFFFu, c, 8);
            c += __shfl_xor_sync(0xFFFFFFFFu, c, 4);
            c += __shfl_xor_sync(0xFFFFFFFFu, c, 2);
            c += __shfl_xor_sync(0xFFFFFFFFu, c, 1);
            ev[sq] = c;
        }
        if (lane == 0 || lane == 16) {
            const int rl = i * STAGE_ROWS + 2 * w + (lane >> 4);
#pragma unroll
            for (int sq = 0; sq < NQ; sq++)
                scores[sq][rl] = ev[sq];
        }

        mbar_arrive(mb_empty + 8 * slot);

        // producer refills this slot for iteration i+NSTAGE
        if (tid == 0 && i + NSTAGE < NITER) {
            mbar_wait(mb_empty + 8 * slot, ph);   // all 256 consumed stage i
            mbar_expect_tx(mb_full + 8 * slot, STAGE_BYTES);
            bulk_copy_g2s(smem_u32(stage[slot]),
                          src + (size_t)(i + NSTAGE) * STAGE_ROWS * D,
                          STAGE_BYTES, mb_full + 8 * slot);
        }
    }
    __syncthreads();

    // ---- Phase B: per-chunk top-10 per query (warps 0..2) ----
    if (w < NQ) {
        float v[8];
        int   gi[8];
#pragma unroll
        for (int s = 0; s < 8; s++) {
            const int rl = lane + 32 * s;
            v[s]  = scores[w][rl];
            gi[s] = rbase + rl;
        }
        const int obase = ((b * NQ + w) * NCHUNK + chunk) * NPOS;
        for (int k = 0; k < NPOS; k++) {
            float bv = v[0]; int bi = gi[0];
#pragma unroll
            for (int s = 1; s < 8; s++)
                if (v[s] > bv) { bv = v[s]; bi = gi[s]; }
#pragma unroll
            for (int off = 16; off; off >>= 1) {
                float v2 = __shfl_xor_sync(0xFFFFFFFFu, bv, off);
                int   i2 = __shfl_xor_sync(0xFFFFFFFFu, bi, off);
                if (v2 > bv || (v2 == bv && i2 < bi)) { bv = v2; bi = i2; }
            }
            if (lane == 0) {
                g_cand_val[obase + k] = bv;
                g_cand_idx[obase + k] = bi;
            }
#pragma unroll
            for (int s = 0; s < 8; s++)
                if (gi[s] == bi) v[s] = -FLT_MAX;
        }
    }
}

// ---------------------------------------------------------------------------
// Kernel B: per-(b,q) merge + JSD. 96 blocks x 256 threads.
//   warp 0:    register-resident top-10 merge of 160 candidates
//   warps 1-3: concurrently stream the 3 z_dis p-rows into smem
//   then all 8 warps: the 10 JSD pairs (p from smem, q-row from global).
// ---------------------------------------------------------------------------
__global__ void __launch_bounds__(256) merge_loss_kernel(
    const float* __restrict__ z_dis,
    const float* __restrict__ z_pos_dis,
    const int*  __restrict__ ridx)
{
    const int bq   = blockIdx.x;
    const int b    = bq / NQ;
    const int q    = bq % NQ;
    const int tid  = threadIdx.x;
    const int w    = tid >> 5;
    const int lane = tid & 31;

    __shared__ int   sel[NPOS];
    __shared__ int   qrow[NQ];
    __shared__ __align__(16) float prow_s[NQ][NPQ];   // 6 KB, 16B-aligned for float4

    const int is64 = detect_is64(ridx, tid);
    if (tid < NQ) qrow[tid] = load_idx(ridx, b * NQ + tid, is64);
    __syncthreads();

    if (w >= 1 && w <= NQ) {
        const int pr = qrow[w - 1];
        const float4* src = (const float4*)(z_dis + ((size_t)b * HW + pr) * NPQ);
        float4* dst = (float4*)prow_s[w - 1];
#pragma unroll
        for (int t = 0; t < 4; t++)
            dst[lane + t * 32] = src[lane + t * 32];
    } else if (w == 0) {
        const int cbase = bq * NCAND;
        float v[5];
        int   gi[5];
#pragma unroll
        for (int s = 0; s < 5; s++) {
            const int j = cbase + lane + s * 32;
            v[s]  = g_cand_val[j];
            gi[s] = g_cand_idx[j];
        }
        for (int k = 0; k < NPOS; k++) {
            float bv = v[0]; int bi = gi[0];
#pragma unroll
            for (int s = 1; s < 5; s++)
                if (v[s] > bv || (v[s] == bv && gi[s] < bi)) { bv = v[s]; bi = gi[s]; }
#pragma unroll
            for (int off = 16; off; off >>= 1) {
                float v2 = __shfl_xor_sync(0xFFFFFFFFu, bv, off);
                int   i2 = __shfl_xor_sync(0xFFFFFFFFu, bi, off);
                if (v2 > bv || (v2 == bv && i2 < bi)) { bv = v2; bi = i2; }
            }
            if (lane == 0) sel[k] = bi;
#pragma unroll
            for (int s = 0; s < 5; s++)
                if (gi[s] == bi) v[s] = -FLT_MAX;
        }
    }
    __syncthreads();

    for (int k = w; k < NPOS; k += 8) {
        const int rb  = 10 * q + k;
        const int pq_ = rb % NQ;
        const int qr  = sel[k];

        const float4* P = (const float4*)prow_s[pq_];
        const float4* Q = (const float4*)(z_pos_dis + ((size_t)b * HW + qr) * NPQ);

        float s = 0.f;
#pragma unroll
        for (int t = 0; t < 4; t++) {
            const float4 pv = P[lane + t * 32];
            const float4 qv = Q[lane + t * 32];
            const float pp[4] = {pv.x, pv.y, pv.z, pv.w};
            const float qq[4] = {qv.x, qv.y, qv.z, qv.w};
#pragma unroll
            for (int e = 0; e < 4; e++) {
                const float p   = pp[e];
                const float qe  = qq[e];
                const float sum = p + qe;
                const float m   = __logf(fminf(fmaxf(0.5f * sum, 1e-7f), 1.0f));
                float t2 = 0.f;
                if (p  > 0.f) t2 += p  * __logf(p);
                if (qe > 0.f) t2 += qe * __logf(qe);
                s += t2 - sum * m;
            }
        }
#pragma unroll
        for (int off = 16; off; off >>= 1)
            s += __shfl_xor_sync(0xFFFFFFFFu, s, off);
        if (lane == 0) g_part[b * NPAIR + rb] = s;
    }
}

// ---------------------------------------------------------------------------
// Kernel C: deterministic fixed-order final reduction and scaling.
// ---------------------------------------------------------------------------
__global__ void __launch_bounds__(256) final_kernel(float* __restrict__ out) {
    const int tid = threadIdx.x;
    float s = 0.f;
    for (int j = tid; j < B * NPAIR; j += 256) s += g_part[j];
    __shared__ float red[256];
    red[tid] = s;
    __syncthreads();
    for (int off = 128; off; off >>= 1) {
        if (tid < off) red[tid] += red[tid + off];
        __syncthreads();
    }
    if (tid == 0) out[0] = red[0] * (0.5f / (float)(B * NPAIR));
}

// ---------------------------------------------------------------------------
extern "C" void kernel_launch(void* const* d_in, const int* in_sizes, int n_in,
                              void* d_out, int out_size)
{
    (void)in_sizes; (void)n_in; (void)out_size;
    const float* z         = (const float*)d_in[0];
    const float* z_pos     = (const float*)d_in[1];
    const float* z_dis     = (const float*)d_in[2];
    const float* z_pos_dis = (const float*)d_in[3];
    const int*   ridx      = (const int*)d_in[4];

    attn_kernel<<<dim3(B, NCHUNK), 256>>>(z, z_pos, ridx);
    merge_loss_kernel<<<B * NQ, 256>>>(z_dis, z_pos_dis, ridx);
    final_kernel<<<1, 256>>>((float*)d_out);
}

// round 17
// speedup vs baseline: 1.0367x; 1.0367x over previous
#include <cuda_runtime.h>
#include <math.h>
#include <float.h>
#include <stdint.h>

#define B      32
#define HW     4096
#define D      256
#define NPQ    512
#define NQ     3
#define NPOS   10
#define NPAIR  30              // NQ * NPOS per batch
#define CHUNK  256             // rows per attn block
#define NCHUNK (HW / CHUNK)    // 16
#define NCAND  (NCHUNK * NPOS) // 160 candidates per (b,q)

#define STAGE_ROWS  16
#define NSTAGE      2
#define NITER       (CHUNK / STAGE_ROWS)          // 16
#define STAGE_BYTES (STAGE_ROWS * D * 4)          // 16384

// ---- scratch (device globals; no allocation allowed) ----
__device__ float g_cand_val[B * NQ * NCAND];
__device__ int   g_cand_idx[B * NQ * NCAND];
__device__ float g_part[B * NPAIR];

// ---------------------------------------------------------------------------
// mbarrier / bulk-copy primitives
// ---------------------------------------------------------------------------
__device__ __forceinline__ uint32_t smem_u32(const void* p) {
    return (uint32_t)__cvta_generic_to_shared(p);
}

__device__ __forceinline__ void mbar_init(uint32_t bar, uint32_t count) {
    asm volatile("mbarrier.init.shared.b64 [%0], %1;" :: "r"(bar), "r"(count) : "memory");
}

__device__ __forceinline__ void mbar_expect_tx(uint32_t bar, uint32_t bytes) {
    asm volatile("mbarrier.arrive.expect_tx.shared.b64 _, [%0], %1;"
                 :: "r"(bar), "r"(bytes) : "memory");
}

__device__ __forceinline__ void mbar_arrive(uint32_t bar) {
    asm volatile("mbarrier.arrive.shared.b64 _, [%0];" :: "r"(bar) : "memory");
}

__device__ __forceinline__ void mbar_wait(uint32_t bar, uint32_t parity) {
    asm volatile(
        "{\n\t"
        ".reg .pred P;\n\t"
        "LWAIT%=:\n\t"
        "mbarrier.try_wait.parity.acquire.cta.shared::cta.b64 P, [%0], %1;\n\t"
        "@!P bra LWAIT%=;\n\t"
        "}"
        :: "r"(bar), "r"(parity) : "memory");
}

__device__ __forceinline__ void bulk_copy_g2s(uint32_t dst_smem, const void* src_gmem,
                                              uint32_t bytes, uint32_t bar) {
    asm volatile(
        "cp.async.bulk.shared::cta.global.mbarrier::complete_tx::bytes [%0], [%1], %2, [%3];"
        :: "r"(dst_smem), "l"(src_gmem), "r"(bytes), "r"(bar) : "memory");
}

// ---------------------------------------------------------------------------
// rand_idx dtype detection, block-local: int64 nonneg (<2^31) -> odd 32-bit
// words of the first 48 entries are all 0. Reads stay within 384 B (valid for
// both int32[96] and int64[96] layouts). Must be called by ALL threads.
// ---------------------------------------------------------------------------
__device__ __forceinline__ int detect_is64(const int* __restrict__ r32, int tid) {
    int v = (tid < 48) ? r32[2 * tid + 1] : 0;
    int any = __syncthreads_or(v != 0);
    return any == 0;
}

__device__ __forceinline__ int load_idx(const int* __restrict__ r32, int i, int is64) {
    return is64 ? r32[2 * i] : r32[i];     // little-endian low word
}

// ---------------------------------------------------------------------------
// Kernel A: attn scores for a 256-row chunk + per-chunk top-10 candidates.
// grid (B, 16) = 512, 256 threads (8 warps), 4 CTAs/SM -> single wave.
// TMA bulk-copy 2-stage pipeline: tid 0 streams 16-row (16 KB) stages of
// z_pos into smem (mbarrier expect_tx / full-empty ring); the 8 warps
// compute 2 rows each per stage from smem (LDS.128, conflict-free), with a
// packed 2-row x 3-query butterfly reduction (18 shuffles).
// Phase B: warps 0..2 extract the chunk-local top-10 per query.
// ---------------------------------------------------------------------------
__global__ void __launch_bounds__(256, 4) attn_kernel(
    const float* __restrict__ z,
    const float* __restrict__ z_pos,
    const int*  __restrict__ ridx)
{
    const int b     = blockIdx.x;
    const int chunk = blockIdx.y;
    const int tid   = threadIdx.x;
    const int w     = tid >> 5;
    const int lane  = tid & 31;

    __shared__ __align__(128) float stage[NSTAGE][STAGE_ROWS * D];   // 32 KB
    __shared__ float scores[NQ][CHUNK];                              // 3 KB
    __shared__ int   qrow[NQ];
    __shared__ __align__(8) unsigned long long mbar[2 * NSTAGE];     // full[s], empty[s]

    const int is64 = detect_is64(ridx, tid);
    if (tid < NQ) qrow[tid] = load_idx(ridx, b * NQ + tid, is64);

    const uint32_t mb_full  = smem_u32(&mbar[0]);
    const uint32_t mb_empty = smem_u32(&mbar[NSTAGE]);
    if (tid == 0) {
#pragma unroll
        for (int s = 0; s < NSTAGE; s++) {
            mbar_init(mb_full  + 8 * s, 1);     // producer arrive+expect_tx
            mbar_init(mb_empty + 8 * s, 256);   // all threads arrive
        }
    }
    __syncthreads();

    // Per-lane query registers: cols [lane*8, lane*8+8)
    const float* zb = z + (size_t)b * HW * D;
    float q[NQ][8];
#pragma unroll
    for (int s = 0; s < NQ; s++) {
        const float4* qp = (const float4*)(zb + (size_t)qrow[s] * D + lane * 8);
        float4 a = qp[0], c = qp[1];
        q[s][0] = a.x; q[s][1] = a.y; q[s][2] = a.z; q[s][3] = a.w;
        q[s][4] = c.x; q[s][5] = c.y; q[s][6] = c.z; q[s][7] = c.w;
    }

    const float* src = z_pos + (size_t)b * HW * D + (size_t)chunk * CHUNK * D;
    const int    rbase = chunk * CHUNK;

    // prologue: fill both stages
    if (tid == 0) {
#pragma unroll
        for (int s = 0; s < NSTAGE; s++) {
            mbar_expect_tx(mb_full + 8 * s, STAGE_BYTES);
            bulk_copy_g2s(smem_u32(stage[s]), src + (size_t)s * STAGE_ROWS * D,
                          STAGE_BYTES, mb_full + 8 * s);
        }
    }

    for (int i = 0; i < NITER; i++) {
        const int      slot = i & (NSTAGE - 1);
        const uint32_t ph   = (uint32_t)((i / NSTAGE) & 1);

        mbar_wait(mb_full + 8 * slot, ph);

        // two rows per warp: local rows 2w, 2w+1 of this stage
        const float* st = stage[slot];
        const float4* r0p = (const float4*)(st + (2 * w)     * D + lane * 8);
        const float4* r1p = (const float4*)(st + (2 * w + 1) * D + lane * 8);
        float4 x0 = r0p[0], x1 = r0p[1];
        float4 y0 = r1p[0], y1 = r1p[1];

        float s0[NQ], s1[NQ];
#pragma unroll
        for (int sq = 0; sq < NQ; sq++) {
            s0[sq] = x0.x * q[sq][0] + x0.y * q[sq][1] + x0.z * q[sq][2] + x0.w * q[sq][3]
                   + x1.x * q[sq][4] + x1.y * q[sq][5] + x1.z * q[sq][6] + x1.w * q[sq][7];
            s1[sq] = y0.x * q[sq][0] + y0.y * q[sq][1] + y0.z * q[sq][2] + y0.w * q[sq][3]
                   + y1.x * q[sq][4] + y1.y * q[sq][5] + y1.z * q[sq][6] + y1.w * q[sq][7];
        }

        // packed 2-row reduce: lanes 0-15 carry row 2w, lanes 16-31 carry row 2w+1
        float ev[NQ];
#pragma unroll
        for (int sq = 0; sq < NQ; sq++) {
            float t0 = s0[sq] + __shfl_xor_sync(0xFFFFFFFFu, s0[sq], 16);
            float t1 = s1[sq] + __shfl_xor_sync(0xFFFFFFFFu, s1[sq], 16);
            float c  = (lane & 16) ? t1 : t0;
            c += __shfl_xor_sync(0xFFFFFFFFu, c, 8);
            c += __shfl_xor_sync(0xFFFFFFFFu, c, 4);
            c += __shfl_xor_sync(0xFFFFFFFFu, c, 2);
            c += __shfl_xor_sync(0xFFFFFFFFu, c, 1);
            ev[sq] = c;
        }
        if (lane == 0 || lane == 16) {
            const int rl = i * STAGE_ROWS + 2 * w + (lane >> 4);
#pragma unroll
            for (int sq = 0; sq < NQ; sq++)
                scores[sq][rl] = ev[sq];
        }

        mbar_arrive(mb_empty + 8 * slot);

        // producer refills this slot for iteration i+NSTAGE
        if (tid == 0 && i + NSTAGE < NITER) {
            mbar_wait(mb_empty + 8 * slot, ph);   // all 256 consumed stage i
            mbar_expect_tx(mb_full + 8 * slot, STAGE_BYTES);
            bulk_copy_g2s(smem_u32(stage[slot]),
                          src + (size_t)(i + NSTAGE) * STAGE_ROWS * D,
                          STAGE_BYTES, mb_full + 8 * slot);
        }
    }
    __syncthreads();

    // ---- Phase B: per-chunk top-10 per query (warps 0..2) ----
    if (w < NQ) {
        float v[8];
        int   gi[8];
#pragma unroll
        for (int s = 0; s < 8; s++) {
            const int rl = lane + 32 * s;
            v[s]  = scores[w][rl];
            gi[s] = rbase + rl;
        }
        const int obase = ((b * NQ + w) * NCHUNK + chunk) * NPOS;
        for (int k = 0; k < NPOS; k++) {
            float bv = v[0]; int bi = gi[0];
#pragma unroll
            for (int s = 1; s < 8; s++)
                if (v[s] > bv) { bv = v[s]; bi = gi[s]; }
#pragma unroll
            for (int off = 16; off; off >>= 1) {
                float v2 = __shfl_xor_sync(0xFFFFFFFFu, bv, off);
                int   i2 = __shfl_xor_sync(0xFFFFFFFFu, bi, off);
                if (v2 > bv || (v2 == bv && i2 < bi)) { bv = v2; bi = i2; }
            }
            if (lane == 0) {
                g_cand_val[obase + k] = bv;
                g_cand_idx[obase + k] = bi;
            }
#pragma unroll
            for (int s = 0; s < 8; s++)
                if (gi[s] == bi) v[s] = -FLT_MAX;
        }
    }
}

// ---------------------------------------------------------------------------
// Kernel B: per-(b,q) merge + JSD. 96 blocks x 256 threads.
//   warp 0:    register-resident top-10 merge of 160 candidates
//   warps 1-3: concurrently stream the 3 z_dis p-rows into smem
//   then all 8 warps: the 10 JSD pairs (p from smem, q-row from global).
// ---------------------------------------------------------------------------
__global__ void __launch_bounds__(256) merge_loss_kernel(
    const float* __restrict__ z_dis,
    const float* __restrict__ z_pos_dis,
    const int*  __restrict__ ridx)
{
    const int bq   = blockIdx.x;
    const int b    = bq / NQ;
    const int q    = bq % NQ;
    const int tid  = threadIdx.x;
    const int w    = tid >> 5;
    const int lane = tid & 31;

    __shared__ int   sel[NPOS];
    __shared__ int   qrow[NQ];
    __shared__ __align__(16) float prow_s[NQ][NPQ];   // 6 KB, 16B-aligned for float4

    const int is64 = detect_is64(ridx, tid);
    if (tid < NQ) qrow[tid] = load_idx(ridx, b * NQ + tid, is64);
    __syncthreads();

    if (w >= 1 && w <= NQ) {
        const int pr = qrow[w - 1];
        const float4* src = (const float4*)(z_dis + ((size_t)b * HW + pr) * NPQ);
        float4* dst = (float4*)prow_s[w - 1];
#pragma unroll
        for (int t = 0; t < 4; t++)
            dst[lane + t * 32] = src[lane + t * 32];
    } else if (w == 0) {
        const int cbase = bq * NCAND;
        float v[5];
        int   gi[5];
#pragma unroll
        for (int s = 0; s < 5; s++) {
            const int j = cbase + lane + s * 32;
            v[s]  = g_cand_val[j];
            gi[s] = g_cand_idx[j];
        }
        for (int k = 0; k < NPOS; k++) {
            float bv = v[0]; int bi = gi[0];
#pragma unroll
            for (int s = 1; s < 5; s++)
                if (v[s] > bv || (v[s] == bv && gi[s] < bi)) { bv = v[s]; bi = gi[s]; }
#pragma unroll
            for (int off = 16; off; off >>= 1) {
                float v2 = __shfl_xor_sync(0xFFFFFFFFu, bv, off);
                int   i2 = __shfl_xor_sync(0xFFFFFFFFu, bi, off);
                if (v2 > bv || (v2 == bv && i2 < bi)) { bv = v2; bi = i2; }
            }
            if (lane == 0) sel[k] = bi;
#pragma unroll
            for (int s = 0; s < 5; s++)
                if (gi[s] == bi) v[s] = -FLT_MAX;
        }
    }
    __syncthreads();

    for (int k = w; k < NPOS; k += 8) {
        const int rb  = 10 * q + k;
        const int pq_ = rb % NQ;
        const int qr  = sel[k];

        const float4* P = (const float4*)prow_s[pq_];
        const float4* Q = (const float4*)(z_pos_dis + ((size_t)b * HW + qr) * NPQ);

        float s = 0.f;
#pragma unroll
        for (int t = 0; t < 4; t++) {
            const float4 pv = P[lane + t * 32];
            const float4 qv = Q[lane + t * 32];
            const float pp[4] = {pv.x, pv.y, pv.z, pv.w};
            const float qq[4] = {qv.x, qv.y, qv.z, qv.w};
#pragma unroll
            for (int e = 0; e < 4; e++) {
                const float p   = pp[e];
                const float qe  = qq[e];
                const float sum = p + qe;
                const float m   = __logf(fminf(fmaxf(0.5f * sum, 1e-7f), 1.0f));
                float t2 = 0.f;
                if (p  > 0.f) t2 += p  * __logf(p);
                if (qe > 0.f) t2 += qe * __logf(qe);
                s += t2 - sum * m;
            }
        }
#pragma unroll
        for (int off = 16; off; off >>= 1)
            s += __shfl_xor_sync(0xFFFFFFFFu, s, off);
        if (lane == 0) g_part[b * NPAIR + rb] = s;
    }
}

// ---------------------------------------------------------------------------
// Kernel C: deterministic fixed-order final reduction and scaling.
// ---------------------------------------------------------------------------
__global__ void __launch_bounds__(256) final_kernel(float* __restrict__ out) {
    const int tid = threadIdx.x;
    float s = 0.f;
    for (int j = tid; j < B * NPAIR; j += 256) s += g_part[j];
    __shared__ float red[256];
    red[tid] = s;
    __syncthreads();
    for (int off = 128; off; off >>= 1) {
        if (tid < off) red[tid] += red[tid + off];
        __syncthreads();
    }
    if (tid == 0) out[0] = red[0] * (0.5f / (float)(B * NPAIR));
}

// ---------------------------------------------------------------------------
extern "C" void kernel_launch(void* const* d_in, const int* in_sizes, int n_in,
                              void* d_out, int out_size)
{
    (void)in_sizes; (void)n_in; (void)out_size;
    const float* z         = (const float*)d_in[0];
    const float* z_pos     = (const float*)d_in[1];
    const float* z_dis     = (const float*)d_in[2];
    const float* z_pos_dis = (const float*)d_in[3];
    const int*   ridx      = (const int*)d_in[4];

    attn_kernel<<<dim3(B, NCHUNK), 256>>>(z, z_pos, ridx);
    merge_loss_kernel<<<B * NQ, 256>>>(z_dis, z_pos_dis, ridx);
    final_kernel<<<1, 256>>>((float*)d_out);
}